// round 1
// baseline (speedup 1.0000x reference)
#include <cuda_runtime.h>
#include <cuda_fp16.h>
#include <cstdint>

// Problem constants
#define NIMG 32
#define CI   128
#define HH   56
#define WW   56
#define CO   256
#define HP   58      // padded H (halo 1 each side)
#define WP   58      // padded W
#define PIX  (HH*WW)             // 3136
#define MTOT (NIMG*PIX)          // 100352
#define KCHUNKS 9                // 3x3 kernel positions, 128 ci each

// fp16 scratch (static device globals: allowed)
__device__ __align__(16) __half g_xh[NIMG*HP*WP*CI];   // NHWC, zero-padded halo (27.55 MB)
__device__ __align__(16) __half g_wh[CO*9*CI];         // [co][kh*3+kw][ci], = round(W*128)

// ---------------- prep kernels ----------------

__global__ void fill_zero_xh() {
    size_t i = (size_t)blockIdx.x * blockDim.x + threadIdx.x;
    size_t n4 = sizeof(g_xh) / 16;
    if (i < n4) reinterpret_cast<uint4*>(g_xh)[i] = make_uint4(0,0,0,0);
}

__global__ void convert_w(const float* __restrict__ W) {
    int i = blockIdx.x * 256 + threadIdx.x;
    if (i >= CO*CI*9) return;
    // W layout: [co][ci][kh][kw]
    int kw = i % 3; int t = i / 3;
    int kh = t % 3; t /= 3;
    int ci = t % CI; int co = t / CI;
    float v = rintf(W[i] * 128.0f);              // exact integer, |v| < 2048 -> exact fp16
    g_wh[(co*9 + kh*3 + kw)*CI + ci] = __float2half_rn(v);
}

// NCHW fp32 -> NHWC(+halo) fp16, one block per (n, h) row
__global__ void transpose_x(const float* __restrict__ x) {
    __shared__ __half s[CI * 58];  // stride 58 halves -> conflict-free-ish
    int h = blockIdx.x;            // 0..55
    int n = blockIdx.y;            // 0..31
    const float* xp = x + ((size_t)n * CI) * PIX + h * WW;
    for (int id = threadIdx.x; id < CI * WW; id += 256) {
        int ci = id / WW, w = id % WW;
        s[ci * 58 + w] = __float2half_rn(xp[(size_t)ci * PIX + w]);
    }
    __syncthreads();
    __half* dst = g_xh + ((size_t)((n*HP + h + 1) * WP + 1)) * CI;
    for (int id = threadIdx.x; id < WW * CI; id += 256) {
        int w = id / CI, ci = id % CI;
        dst[(size_t)w * CI + ci] = s[ci * 58 + w];
    }
}

// ---------------- GEMM kernel ----------------
// C[pix, co] = sum_{kc=0..8} A_kc[pix, 128ci] * B_kc[co, 128ci]^T
// CTA: 128 pix x 128 co, 8 warps (4m x 2n), warp tile 32x64, mma m16n8k16

#define ROWB   272                 // smem bytes per row (256 data + 16 pad)
#define TILEB  (128 * ROWB)        // 34816 bytes per operand tile
#define STAGEB (2 * TILEB)         // A+B per stage
#define SMEM_DYN (1024 + 2 * STAGEB)   // 512 abase + 512 bq + 2 stages = 140288

__device__ __forceinline__ void ldsm_x4(uint32_t addr, uint32_t& r0, uint32_t& r1,
                                        uint32_t& r2, uint32_t& r3) {
    asm volatile("ldmatrix.sync.aligned.m8n8.x4.shared.b16 {%0,%1,%2,%3}, [%4];\n"
                 : "=r"(r0), "=r"(r1), "=r"(r2), "=r"(r3) : "r"(addr));
}

__global__ void __launch_bounds__(256, 1) qconv_gemm(const float* __restrict__ bias,
                                                     float* __restrict__ out) {
    extern __shared__ char smem[];
    uint32_t* abase = reinterpret_cast<uint32_t*>(smem);        // [128] byte offsets into g_xh
    float*    bq    = reinterpret_cast<float*>(smem + 512);     // [128] quantized bias
    const uint32_t smem_u32 = (uint32_t)__cvta_generic_to_shared(smem);

    const int tid = threadIdx.x;
    const int m_base  = blockIdx.x * 128;
    const int co_base = blockIdx.y * 128;

    if (tid < 128) {
        int p = m_base + tid;
        int ni = p / PIX; int rem = p - ni * PIX;
        int h = rem / WW; int w = rem - h * WW;
        abase[tid] = (uint32_t)(((ni*HP + h) * WP + w) * (CI * 2));  // bytes, at kh=kw=0
        bq[tid] = rintf(bias[co_base + tid] * 128.0f);
    }
    __syncthreads();

    const char* xh = reinterpret_cast<const char*>(g_xh);
    const char* wh = reinterpret_cast<const char*>(g_wh);

    auto load_tile = [&](int kc, int stage) {
        int kh = kc / 3, kw = kc - kh * 3;
        uint32_t off = (uint32_t)((kh * WP + kw) * (CI * 2));
        uint32_t sA = smem_u32 + 1024 + stage * STAGEB;
        uint32_t sB = sA + TILEB;
        #pragma unroll
        for (int i = 0; i < 8; i++) {
            int id = tid + 256 * i;
            int row = id >> 4;
            int ch  = (id & 15) * 16;
            const char* srcA = xh + abase[row] + off + ch;
            uint32_t dA = sA + row * ROWB + ch;
            asm volatile("cp.async.cg.shared.global [%0], [%1], 16;\n" :: "r"(dA), "l"(srcA));
            const char* srcB = wh + (size_t)((co_base + row) * 9 + kc) * (CI * 2) + ch;
            uint32_t dB = sB + row * ROWB + ch;
            asm volatile("cp.async.cg.shared.global [%0], [%1], 16;\n" :: "r"(dB), "l"(srcB));
        }
        asm volatile("cp.async.commit_group;\n" ::: "memory");
    };

    const int warp = tid >> 5, lane = tid & 31;
    const int warp_m = (warp & 3) * 32;
    const int warp_n = (warp >> 2) * 64;

    float acc[2][8][4];
    #pragma unroll
    for (int i = 0; i < 2; i++)
        #pragma unroll
        for (int j = 0; j < 8; j++)
            #pragma unroll
            for (int k = 0; k < 4; k++) acc[i][j][k] = 0.0f;

    // per-thread ldmatrix base offsets (within a tile)
    const uint32_t aoff0 = (uint32_t)((warp_m + (lane & 15)) * ROWB + (lane >> 4) * 16);
    const uint32_t boff0 = (uint32_t)((warp_n + (lane & 7) + ((lane >> 4) << 3)) * ROWB
                                      + ((lane >> 3) & 1) * 16);

    load_tile(0, 0);

    for (int kc = 0; kc < KCHUNKS; kc++) {
        asm volatile("cp.async.wait_group 0;\n" ::: "memory");
        __syncthreads();
        if (kc < KCHUNKS - 1) load_tile(kc + 1, (kc + 1) & 1);

        uint32_t sA = smem_u32 + 1024 + (kc & 1) * STAGEB;
        uint32_t sB = sA + TILEB;

        #pragma unroll
        for (int k16 = 0; k16 < 8; k16++) {
            uint32_t a[2][4];
            #pragma unroll
            for (int mf = 0; mf < 2; mf++)
                ldsm_x4(sA + aoff0 + mf * (16 * ROWB) + k16 * 32,
                        a[mf][0], a[mf][1], a[mf][2], a[mf][3]);
            uint32_t b[8][2];
            #pragma unroll
            for (int j = 0; j < 4; j++) {
                uint32_t r0, r1, r2, r3;
                ldsm_x4(sB + boff0 + j * (16 * ROWB) + k16 * 32, r0, r1, r2, r3);
                b[2*j][0] = r0; b[2*j][1] = r1; b[2*j+1][0] = r2; b[2*j+1][1] = r3;
            }
            #pragma unroll
            for (int mf = 0; mf < 2; mf++)
                #pragma unroll
                for (int nf = 0; nf < 8; nf++) {
                    asm volatile(
                        "mma.sync.aligned.m16n8k16.row.col.f32.f16.f16.f32 "
                        "{%0,%1,%2,%3}, {%4,%5,%6,%7}, {%8,%9}, {%0,%1,%2,%3};\n"
                        : "+f"(acc[mf][nf][0]), "+f"(acc[mf][nf][1]),
                          "+f"(acc[mf][nf][2]), "+f"(acc[mf][nf][3])
                        : "r"(a[mf][0]), "r"(a[mf][1]), "r"(a[mf][2]), "r"(a[mf][3]),
                          "r"(b[nf][0]), "r"(b[nf][1]));
                }
        }
        __syncthreads();
    }

    // epilogue: out[n][co][h][w] = acc/128 + round(b*128)
    const float inv = 0.0078125f;
    #pragma unroll
    for (int mf = 0; mf < 2; mf++) {
        #pragma unroll
        for (int hsel = 0; hsel < 2; hsel++) {
            int m = warp_m + mf * 16 + (lane >> 2) + hsel * 8;
            int p = m_base + m;
            int ni = p / PIX; int rem = p - ni * PIX;
            int h = rem / WW; int w = rem - h * WW;
            float* op = out + (size_t)ni * CO * PIX + h * WW + w;
            #pragma unroll
            for (int nf = 0; nf < 8; nf++) {
                int col = warp_n + nf * 8 + 2 * (lane & 3);
                int co  = co_base + col;
                op[(size_t)co * PIX]       = acc[mf][nf][hsel*2 + 0] * inv + bq[col];
                op[(size_t)(co + 1) * PIX] = acc[mf][nf][hsel*2 + 1] * inv + bq[col + 1];
            }
        }
    }
}

// ---------------- launch ----------------
extern "C" void kernel_launch(void* const* d_in, const int* in_sizes, int n_in,
                              void* d_out, int out_size) {
    const float* x = (const float*)d_in[0];
    const float* W = (const float*)d_in[1];
    const float* b = (const float*)d_in[2];
    float* out = (float*)d_out;

    {
        size_t n4 = sizeof(g_xh) / 16;
        int blocks = (int)((n4 + 255) / 256);
        fill_zero_xh<<<blocks, 256>>>();
    }
    convert_w<<<(CO*CI*9 + 255) / 256, 256>>>(W);
    transpose_x<<<dim3(HH, NIMG), 256>>>(x);

    cudaFuncSetAttribute(qconv_gemm, cudaFuncAttributeMaxDynamicSharedMemorySize, SMEM_DYN);
    qconv_gemm<<<dim3(MTOT / 128, CO / 128), 256, SMEM_DYN>>>(b, out);
}

// round 3
// speedup vs baseline: 1.0130x; 1.0130x over previous
#include <cuda_runtime.h>
#include <cuda_fp16.h>
#include <cstdint>

// ---------------- problem constants ----------------
#define NIMG 32
#define CI   128
#define HH   56
#define WW   56
#define CO   256
#define HP   58
#define WP   58
#define PIX  (HH*WW)          // 3136
#define MTOT (NIMG*PIX)       // 100352

// fp16 scratch (static device globals: allowed)
__device__ __align__(1024) __half g_xh[(size_t)NIMG*HP*WP*CI];  // NHWC + halo
__device__ __align__(1024) __half g_wh[(size_t)9*CO*CI];        // [kc][co][ci]

// ---------------- prep kernels ----------------
__global__ void fill_halo() {
    int n = blockIdx.x, hp = blockIdx.y;
    uint4 z = make_uint4(0, 0, 0, 0);
    __half* base = g_xh + ((size_t)(n * HP + hp)) * WP * CI;
    if (hp == 0 || hp == HP - 1) {
        for (int i = threadIdx.x; i < WP * CI / 8; i += blockDim.x)
            reinterpret_cast<uint4*>(base)[i] = z;
    } else {
        if (threadIdx.x < 16)
            reinterpret_cast<uint4*>(base)[threadIdx.x] = z;
        else if (threadIdx.x < 32)
            reinterpret_cast<uint4*>(base + (size_t)(WP - 1) * CI)[threadIdx.x - 16] = z;
    }
}

__global__ void convert_w(const float* __restrict__ W) {
    int i = blockIdx.x * 256 + threadIdx.x;
    if (i >= CO * CI * 9) return;
    // W layout: [co][ci][kh][kw]
    int kw = i % 3; int t = i / 3;
    int kh = t % 3; t /= 3;
    int ci = t % CI; int co = t / CI;
    float v = rintf(W[i] * 128.0f);              // exact integer, exact in fp16
    g_wh[(size_t)((kh * 3 + kw) * CO + co) * CI + ci] = __float2half_rn(v);
}

// NCHW fp32 -> NHWC(+halo) fp16
__global__ void transpose_x(const float* __restrict__ x) {
    __shared__ __half s[CI * 58];
    int h = blockIdx.x, n = blockIdx.y;
    const float* xp = x + ((size_t)n * CI) * PIX + h * WW;
    for (int id = threadIdx.x; id < CI * WW; id += 256) {
        int ci = id / WW, w = id % WW;
        s[ci * 58 + w] = __float2half_rn(xp[(size_t)ci * PIX + w]);
    }
    __syncthreads();
    __half* dst = g_xh + ((size_t)((n * HP + h + 1) * WP + 1)) * CI;
    for (int id = threadIdx.x; id < WW * CI; id += 256) {
        int w = id / CI, ci = id % CI;
        dst[(size_t)w * CI + ci] = s[ci * 58 + w];
    }
}

// ---------------- GEMM (HMMA, 4-stage cp.async pipeline) ----------------
// CTA: 128 pix x 128 co. K: 18 chunks of 64 ci (9 taps x 2 halves).
// 8 warps (4m x 2n), warp tile 32x64, mma m16n8k16 f32.f16.
// smem: [0..512) bq, then 4 stages of (128 A-rows + 128 B-rows) x 144B.

#define ROWB    144                 // 128B data + 16B pad (4-bank shift/row)
#define BOFF    (128 * ROWB)        // B tile offset within a stage (18432)
#define STAGE   (256 * ROWB)        // 36864
#define NSTAGE  4
#define NT      18
#define HDR     512
#define SMEM_DYN (HDR + NSTAGE * STAGE)   // 147968

__device__ __forceinline__ void ldsm_x4(uint32_t addr, uint32_t& r0, uint32_t& r1,
                                        uint32_t& r2, uint32_t& r3) {
    asm volatile("ldmatrix.sync.aligned.m8n8.x4.shared.b16 {%0,%1,%2,%3}, [%4];\n"
                 : "=r"(r0), "=r"(r1), "=r"(r2), "=r"(r3) : "r"(addr));
}

__global__ void __launch_bounds__(256, 1) qconv_gemm(const float* __restrict__ bias,
                                                     float* __restrict__ out) {
    extern __shared__ char smem[];
    float* bq = reinterpret_cast<float*>(smem);
    const uint32_t sb = (uint32_t)__cvta_generic_to_shared(smem);

    const int tid = threadIdx.x;
    const int m_base  = blockIdx.x * 128;
    const int co_base = blockIdx.y * 128;

    if (tid < 128) bq[tid] = rintf(bias[co_base + tid] * 128.0f);

    // per-thread cp.async endpoints: 4 A-pieces + 4 B-pieces per stage
    const char* xh = reinterpret_cast<const char*>(g_xh);
    const char* wh = reinterpret_cast<const char*>(g_wh);
    const char* aSrc[4]; const char* bSrc[4];
    uint32_t aDst[4], bDst[4];
    #pragma unroll
    for (int i = 0; i < 4; i++) {
        int id = tid + 256 * i;
        int row = id >> 3;            // 0..127
        int ch  = (id & 7) * 16;      // 0..112
        int p = m_base + row;
        int ni = p / PIX; int rem = p - ni * PIX;
        int h = rem / WW; int w = rem - h * WW;
        aSrc[i] = xh + ((size_t)((ni * HP + h) * WP + w)) * 256 + ch;  // window top-left
        aDst[i] = sb + HDR + row * ROWB + ch;
        bSrc[i] = wh + ((size_t)(co_base + row)) * 256 + ch;
        bDst[i] = sb + HDR + BOFF + row * ROWB + ch;
    }

    // issue one K-chunk's loads into a stage slot; chunk t: kc = t>>1, half = t&1
    auto issue = [&](int t, int slot) {
        int kc = t >> 1, hf = t & 1;
        int kh = kc / 3, kw = kc - kh * 3;
        uint32_t aoff = (uint32_t)((kh * WP + kw) * 256 + hf * 128);
        uint32_t boff = (uint32_t)(kc * (CO * 256) + hf * 128);
        uint32_t so = slot * STAGE;
        #pragma unroll
        for (int i = 0; i < 4; i++)
            asm volatile("cp.async.cg.shared.global [%0], [%1], 16;\n"
                         :: "r"(aDst[i] + so), "l"(aSrc[i] + aoff));
        #pragma unroll
        for (int i = 0; i < 4; i++)
            asm volatile("cp.async.cg.shared.global [%0], [%1], 16;\n"
                         :: "r"(bDst[i] + so), "l"(bSrc[i] + boff));
        asm volatile("cp.async.commit_group;\n" ::: "memory");
    };

    const int warp = tid >> 5, lane = tid & 31;
    const int warp_m = (warp & 3) * 32;
    const int warp_n = (warp >> 2) * 64;

    float acc[2][8][4];
    #pragma unroll
    for (int i = 0; i < 2; i++)
        #pragma unroll
        for (int j = 0; j < 8; j++)
            #pragma unroll
            for (int k = 0; k < 4; k++) acc[i][j][k] = 0.0f;

    const uint32_t aoff0 = (uint32_t)((warp_m + (lane & 15)) * ROWB + (lane >> 4) * 16);
    const uint32_t boff0 = (uint32_t)(BOFF + (warp_n + (lane & 7) + ((lane >> 4) << 3)) * ROWB
                                      + ((lane >> 3) & 1) * 16);

    // prologue: fill 3 of 4 stages
    issue(0, 0); issue(1, 1); issue(2, 2);

    #pragma unroll 1
    for (int t = 0; t < NT; t++) {
        asm volatile("cp.async.wait_group 2;\n" ::: "memory");
        __syncthreads();
        if (t + 3 < NT) issue(t + 3, (t + 3) & 3);
        else asm volatile("cp.async.commit_group;\n" ::: "memory");  // keep group count

        uint32_t sA = sb + HDR + (t & 3) * STAGE;
        #pragma unroll
        for (int k16 = 0; k16 < 4; k16++) {
            uint32_t a[2][4];
            #pragma unroll
            for (int mf = 0; mf < 2; mf++)
                ldsm_x4(sA + aoff0 + mf * (16 * ROWB) + k16 * 32,
                        a[mf][0], a[mf][1], a[mf][2], a[mf][3]);
            uint32_t b[8][2];
            #pragma unroll
            for (int j = 0; j < 4; j++) {
                uint32_t r0, r1, r2, r3;
                ldsm_x4(sA + boff0 + j * (16 * ROWB) + k16 * 32, r0, r1, r2, r3);
                b[2*j][0] = r0; b[2*j][1] = r1; b[2*j+1][0] = r2; b[2*j+1][1] = r3;
            }
            #pragma unroll
            for (int mf = 0; mf < 2; mf++)
                #pragma unroll
                for (int nf = 0; nf < 8; nf++) {
                    asm volatile(
                        "mma.sync.aligned.m16n8k16.row.col.f32.f16.f16.f32 "
                        "{%0,%1,%2,%3}, {%4,%5,%6,%7}, {%8,%9}, {%0,%1,%2,%3};\n"
                        : "+f"(acc[mf][nf][0]), "+f"(acc[mf][nf][1]),
                          "+f"(acc[mf][nf][2]), "+f"(acc[mf][nf][3])
                        : "r"(a[mf][0]), "r"(a[mf][1]), "r"(a[mf][2]), "r"(a[mf][3]),
                          "r"(b[nf][0]), "r"(b[nf][1]));
                }
        }
    }

    // epilogue: out[n][co][h][w] = acc/128 + round(b*128)
    const float inv = 0.0078125f;
    #pragma unroll
    for (int mf = 0; mf < 2; mf++) {
        #pragma unroll
        for (int hsel = 0; hsel < 2; hsel++) {
            int m = warp_m + mf * 16 + (lane >> 2) + hsel * 8;
            int p = m_base + m;
            int ni = p / PIX; int rem = p - ni * PIX;
            int h = rem / WW; int w = rem - h * WW;
            float* op = out + (size_t)ni * CO * PIX + h * WW + w;
            #pragma unroll
            for (int nf = 0; nf < 8; nf++) {
                int col = warp_n + nf * 8 + 2 * (lane & 3);
                int co  = co_base + col;
                op[(size_t)co * PIX]       = acc[mf][nf][hsel*2 + 0] * inv + bq[col];
                op[(size_t)(co + 1) * PIX] = acc[mf][nf][hsel*2 + 1] * inv + bq[col + 1];
            }
        }
    }
}

// ---------------- launch ----------------
extern "C" void kernel_launch(void* const* d_in, const int* in_sizes, int n_in,
                              void* d_out, int out_size) {
    const float* x = (const float*)d_in[0];
    const float* W = (const float*)d_in[1];
    const float* b = (const float*)d_in[2];
    float* out = (float*)d_out;

    fill_halo<<<dim3(NIMG, HP), 128>>>();
    convert_w<<<(CO * CI * 9 + 255) / 256, 256>>>(W);
    transpose_x<<<dim3(HH, NIMG), 256>>>(x);

    cudaFuncSetAttribute(qconv_gemm, cudaFuncAttributeMaxDynamicSharedMemorySize, SMEM_DYN);
    qconv_gemm<<<dim3(MTOT / 128, CO / 128), 256, SMEM_DYN>>>(b, out);
}

// round 4
// speedup vs baseline: 1.0914x; 1.0774x over previous
#include <cuda_runtime.h>
#include <cuda_fp16.h>
#include <cstdint>

// ---------------- problem constants ----------------
#define NIMG 32
#define CI   128
#define HH   56
#define WW   56
#define CO   256
#define HP   58
#define WP   58
#define PIX  (HH*WW)          // 3136
#define MTOT (NIMG*PIX)       // 100352

// fp16 scratch (static device globals: allowed)
__device__ __align__(1024) __half g_xh[(size_t)NIMG*HP*WP*CI];  // NHWC + halo
__device__ __align__(1024) __half g_wh[(size_t)9*CO*CI];        // [kc][co][ci]

// ---------------- prep kernels ----------------
__global__ void fill_halo() {
    int n = blockIdx.x, hp = blockIdx.y;
    uint4 z = make_uint4(0, 0, 0, 0);
    __half* base = g_xh + ((size_t)(n * HP + hp)) * WP * CI;
    if (hp == 0 || hp == HP - 1) {
        for (int i = threadIdx.x; i < WP * CI / 8; i += blockDim.x)
            reinterpret_cast<uint4*>(base)[i] = z;
    } else {
        if (threadIdx.x < 16)
            reinterpret_cast<uint4*>(base)[threadIdx.x] = z;
        else if (threadIdx.x < 32)
            reinterpret_cast<uint4*>(base + (size_t)(WP - 1) * CI)[threadIdx.x - 16] = z;
    }
}

__global__ void convert_w(const float* __restrict__ W) {
    int i = blockIdx.x * 256 + threadIdx.x;
    if (i >= CO * CI * 9) return;
    // W layout: [co][ci][kh][kw]
    int kw = i % 3; int t = i / 3;
    int kh = t % 3; t /= 3;
    int ci = t % CI; int co = t / CI;
    float v = rintf(W[i] * 128.0f);              // exact integer, exact in fp16
    g_wh[(size_t)((kh * 3 + kw) * CO + co) * CI + ci] = __float2half_rn(v);
}

// NCHW fp32 -> NHWC(+halo) fp16
__global__ void transpose_x(const float* __restrict__ x) {
    __shared__ __half s[CI * 58];
    int h = blockIdx.x, n = blockIdx.y;
    const float* xp = x + ((size_t)n * CI) * PIX + h * WW;
    for (int id = threadIdx.x; id < CI * WW; id += 256) {
        int ci = id / WW, w = id % WW;
        s[ci * 58 + w] = __float2half_rn(xp[(size_t)ci * PIX + w]);
    }
    __syncthreads();
    __half* dst = g_xh + ((size_t)((n * HP + h + 1) * WP + 1)) * CI;
    for (int id = threadIdx.x; id < WW * CI; id += 256) {
        int w = id / CI, ci = id % CI;
        dst[(size_t)w * CI + ci] = s[ci * 58 + w];
    }
}

// ---------------- GEMM (HMMA, warp tile 64x64) ----------------
// CTA: 128 pix x 256 co. K: 18 chunks of 64 ci (9 taps x 2 halves).
// 8 warps in 2m x 4n grid of 64x64 warp tiles, mma m16n8k16 f32.f16.
// smem: [0..1024) bq[256], then 3 stages of (128 A-rows + 256 B-rows) x 144B.

#define ROWB    144                 // 128B data + 16B pad (4-bank shift/row)
#define BOFF    (128 * ROWB)        // B tile offset within a stage
#define STAGE   (384 * ROWB)        // 55296
#define NSTAGE  3
#define NT      18
#define HDR     1024
#define SMEM_DYN (HDR + NSTAGE * STAGE)   // 166912

__device__ __forceinline__ void ldsm_x4(uint32_t addr, uint32_t& r0, uint32_t& r1,
                                        uint32_t& r2, uint32_t& r3) {
    asm volatile("ldmatrix.sync.aligned.m8n8.x4.shared.b16 {%0,%1,%2,%3}, [%4];\n"
                 : "=r"(r0), "=r"(r1), "=r"(r2), "=r"(r3) : "r"(addr));
}

__global__ void __launch_bounds__(256, 1) qconv_gemm(const float* __restrict__ bias,
                                                     float* __restrict__ out) {
    extern __shared__ char smem[];
    float* bq = reinterpret_cast<float*>(smem);
    const uint32_t sb = (uint32_t)__cvta_generic_to_shared(smem);

    const int tid = threadIdx.x;
    const int m_base = blockIdx.x * 128;

    bq[tid] = rintf(bias[tid] * 128.0f);

    // per-thread cp.async endpoints: 4 A-pieces + 8 B-pieces per stage
    const char* xh = reinterpret_cast<const char*>(g_xh);
    const char* wh = reinterpret_cast<const char*>(g_wh);
    const char* aSrc[4]; const char* bSrc[8];
    uint32_t aDst[4], bDst[8];
    #pragma unroll
    for (int i = 0; i < 4; i++) {
        int id = tid + 256 * i;
        int row = id >> 3;            // 0..127
        int ch  = (id & 7) * 16;      // 0..112
        int p = m_base + row;
        int ni = p / PIX; int rem = p - ni * PIX;
        int h = rem / WW; int w = rem - h * WW;
        aSrc[i] = xh + ((size_t)((ni * HP + h) * WP + w)) * 256 + ch;  // window top-left
        aDst[i] = sb + HDR + row * ROWB + ch;
    }
    #pragma unroll
    for (int i = 0; i < 8; i++) {
        int id = tid + 256 * i;
        int row = id >> 3;            // 0..255
        int ch  = (id & 7) * 16;
        bSrc[i] = wh + (size_t)row * 256 + ch;
        bDst[i] = sb + HDR + BOFF + row * ROWB + ch;
    }

    // issue one K-chunk's loads into a stage slot; chunk t: kc = t>>1, half = t&1
    auto issue = [&](int t, int slot) {
        int kc = t >> 1, hf = t & 1;
        int kh = kc / 3, kw = kc - kh * 3;
        uint32_t aoff = (uint32_t)((kh * WP + kw) * 256 + hf * 128);
        uint32_t boff = (uint32_t)(kc * (CO * 256) + hf * 128);
        uint32_t so = slot * STAGE;
        #pragma unroll
        for (int i = 0; i < 4; i++)
            asm volatile("cp.async.cg.shared.global [%0], [%1], 16;\n"
                         :: "r"(aDst[i] + so), "l"(aSrc[i] + aoff));
        #pragma unroll
        for (int i = 0; i < 8; i++)
            asm volatile("cp.async.cg.shared.global [%0], [%1], 16;\n"
                         :: "r"(bDst[i] + so), "l"(bSrc[i] + boff));
        asm volatile("cp.async.commit_group;\n" ::: "memory");
    };

    const int warp = tid >> 5, lane = tid & 31;
    const int warp_m = (warp & 1) * 64;
    const int warp_n = (warp >> 1) * 64;

    float acc[4][8][4];
    #pragma unroll
    for (int i = 0; i < 4; i++)
        #pragma unroll
        for (int j = 0; j < 8; j++)
            #pragma unroll
            for (int k = 0; k < 4; k++) acc[i][j][k] = 0.0f;

    const uint32_t aoff0 = (uint32_t)((warp_m + (lane & 15)) * ROWB + (lane >> 4) * 16);
    const uint32_t boff0 = (uint32_t)(BOFF + (warp_n + (lane & 7) + ((lane >> 4) << 3)) * ROWB
                                      + ((lane >> 3) & 1) * 16);

    // prologue: fill 2 of 3 stages
    issue(0, 0); issue(1, 1);

    #pragma unroll 1
    for (int t = 0; t < NT; t++) {
        asm volatile("cp.async.wait_group 1;\n" ::: "memory");
        __syncthreads();
        int tn = t + 2;
        if (tn < NT) issue(tn, tn - (tn / 3) * 3);
        else asm volatile("cp.async.commit_group;\n" ::: "memory");  // keep group count

        uint32_t sA = sb + HDR + (t - (t / 3) * 3) * STAGE;
        #pragma unroll
        for (int k16 = 0; k16 < 4; k16++) {
            uint32_t a[4][4];
            #pragma unroll
            for (int mf = 0; mf < 4; mf++)
                ldsm_x4(sA + aoff0 + mf * (16 * ROWB) + k16 * 32,
                        a[mf][0], a[mf][1], a[mf][2], a[mf][3]);
            uint32_t b[8][2];
            #pragma unroll
            for (int j = 0; j < 4; j++) {
                uint32_t r0, r1, r2, r3;
                ldsm_x4(sA + boff0 + j * (16 * ROWB) + k16 * 32, r0, r1, r2, r3);
                b[2*j][0] = r0; b[2*j][1] = r1; b[2*j+1][0] = r2; b[2*j+1][1] = r3;
            }
            #pragma unroll
            for (int mf = 0; mf < 4; mf++)
                #pragma unroll
                for (int nf = 0; nf < 8; nf++) {
                    asm volatile(
                        "mma.sync.aligned.m16n8k16.row.col.f32.f16.f16.f32 "
                        "{%0,%1,%2,%3}, {%4,%5,%6,%7}, {%8,%9}, {%0,%1,%2,%3};\n"
                        : "+f"(acc[mf][nf][0]), "+f"(acc[mf][nf][1]),
                          "+f"(acc[mf][nf][2]), "+f"(acc[mf][nf][3])
                        : "r"(a[mf][0]), "r"(a[mf][1]), "r"(a[mf][2]), "r"(a[mf][3]),
                          "r"(b[nf][0]), "r"(b[nf][1]));
                }
        }
    }

    // epilogue: out[n][co][h][w] = acc/128 + round(b*128)
    const float inv = 0.0078125f;
    #pragma unroll
    for (int mf = 0; mf < 4; mf++) {
        #pragma unroll
        for (int hsel = 0; hsel < 2; hsel++) {
            int m = warp_m + mf * 16 + (lane >> 2) + hsel * 8;
            int p = m_base + m;
            int ni = p / PIX; int rem = p - ni * PIX;
            int h = rem / WW; int w = rem - h * WW;
            float* op = out + (size_t)ni * CO * PIX + h * WW + w;
            #pragma unroll
            for (int nf = 0; nf < 8; nf++) {
                int col = warp_n + nf * 8 + 2 * (lane & 3);
                op[(size_t)col * PIX]       = acc[mf][nf][hsel*2 + 0] * inv + bq[col];
                op[(size_t)(col + 1) * PIX] = acc[mf][nf][hsel*2 + 1] * inv + bq[col + 1];
            }
        }
    }
}

// ---------------- launch ----------------
extern "C" void kernel_launch(void* const* d_in, const int* in_sizes, int n_in,
                              void* d_out, int out_size) {
    const float* x = (const float*)d_in[0];
    const float* W = (const float*)d_in[1];
    const float* b = (const float*)d_in[2];
    float* out = (float*)d_out;

    fill_halo<<<dim3(NIMG, HP), 128>>>();
    convert_w<<<(CO * CI * 9 + 255) / 256, 256>>>(W);
    transpose_x<<<dim3(HH, NIMG), 256>>>(x);

    cudaFuncSetAttribute(qconv_gemm, cudaFuncAttributeMaxDynamicSharedMemorySize, SMEM_DYN);
    qconv_gemm<<<dim3(MTOT / 128), 256, SMEM_DYN>>>(b, out);
}